// round 11
// baseline (speedup 1.0000x reference)
#include <cuda_runtime.h>
#include <cuda_bf16.h>

// Problem constants (fixed by the dataset)
#define MAXN 100352
#define MAXE 1605632
#define H 64

// ---------------- device scratch (no allocations allowed) ----------------
__device__ float g_hp [MAXN * H];   // pre-scaled features  h' = dinv * h
__device__ float g_a  [MAXN * H];   // aggregated features (gather output)
__device__ int   g_deg   [MAXN];
__device__ float g_dinv  [MAXN];
__device__ int   g_rowptr[MAXN + 1];
__device__ int   g_cursor[MAXN];
__device__ int   g_csr   [MAXE];    // src index per CSR slot (grouped by dst)
__device__ int   g_bsums [1024];

// ---------------- CSR build ----------------

// vectorized degree count: int4 per thread (4 edges, 4 atomics)
__global__ void k_count(const int* __restrict__ dst, int E) {
    int i = blockIdx.x * blockDim.x + threadIdx.x;
    int e = i * 4;
    if (e + 3 < E) {
        int4 d = __ldg((const int4*)dst + i);
        atomicAdd(&g_deg[d.x], 1);
        atomicAdd(&g_deg[d.y], 1);
        atomicAdd(&g_deg[d.z], 1);
        atomicAdd(&g_deg[d.w], 1);
    } else {
        for (; e < E; e++) atomicAdd(&g_deg[dst[e]], 1);
    }
}

// exclusive scan of g_deg -> g_rowptr (warp-shuffle scan); also dinv = rsqrt(deg+1)
__global__ void k_scan1(int N) {
    __shared__ int wsum[32];
    int t = threadIdx.x, i = blockIdx.x * 1024 + t;
    int lane = t & 31, wid = t >> 5;
    int v = (i < N) ? g_deg[i] : 0;
    if (i < N) g_dinv[i] = rsqrtf((float)v + 1.0f);
    int x = v;
#pragma unroll
    for (int off = 1; off < 32; off <<= 1) {
        int y = __shfl_up_sync(0xffffffffu, x, off);
        if (lane >= off) x += y;
    }
    if (lane == 31) wsum[wid] = x;
    __syncthreads();
    if (wid == 0) {
        int w = wsum[lane];
#pragma unroll
        for (int off = 1; off < 32; off <<= 1) {
            int y = __shfl_up_sync(0xffffffffu, w, off);
            if (lane >= off) w += y;
        }
        wsum[lane] = w;
    }
    __syncthreads();
    int boff = (wid > 0) ? wsum[wid - 1] : 0;
    int incl = x + boff;
    if (i < N) g_rowptr[i] = incl - v;          // exclusive
    if (t == 1023) g_bsums[blockIdx.x] = incl;  // block total
}

// adds global block offsets (computed directly from g_bsums) + inits cursors.
// Replaces the old scan2+scan3 pair: warp 0 sums bsums[0..b) (<=97 ints).
__global__ void k_scan3(int N, int E) {
    __shared__ int s_off;
    int b = blockIdx.x, t = threadIdx.x;
    if (t < 32) {
        int sum = 0;
        for (int j = t; j < b; j += 32) sum += g_bsums[j];
#pragma unroll
        for (int off = 16; off; off >>= 1)
            sum += __shfl_xor_sync(0xffffffffu, sum, off);
        if (t == 0) s_off = sum;
    }
    __syncthreads();
    int i = b * 1024 + t;
    if (i < N) {
        int rp = g_rowptr[i] + s_off;
        g_rowptr[i] = rp;
        g_cursor[i] = rp;                       // fill cursors start at row base
    }
    if (i == 0) g_rowptr[N] = E;
}

// fused: CSR fill (idx < E) + node encoder (idx < N*H).
// hp = dinv * relu(x @ Wn + bn)
__global__ void k_fill_encode(const int* __restrict__ src, const int* __restrict__ dst,
                              const float* __restrict__ x,
                              const float* __restrict__ Wn,
                              const float* __restrict__ bn, int N, int E) {
    int idx = blockIdx.x * blockDim.x + threadIdx.x;
    if (idx < E) {
        int pos = atomicAdd(&g_cursor[dst[idx]], 1);
        g_csr[pos] = src[idx];
    }
    if (idx < N * H) {
        int n = idx >> 6, c = idx & 63;
        const float* xr = x + n * 5;
        float acc = __ldg(&bn[c]);
#pragma unroll
        for (int j = 0; j < 5; j++) acc = fmaf(__ldg(&xr[j]), __ldg(&Wn[j * H + c]), acc);
        g_hp[idx] = g_dinv[n] * fmaxf(acc, 0.0f);
    }
}

// ---------------- feature pipeline ----------------

// a_n = dinv_n * ( sum_{s in in(n)} h'_s + h'_n ) ; warp per node.
// Half-warp per edge: lanes 0-15 even edges, 16-31 odd edges, float4/lane.
// 8-edge unroll -> 4 independent LDG.128 in flight per half-warp.
__global__ void k_gather(int N) {
    int warp = (blockIdx.x * blockDim.x + threadIdx.x) >> 5;
    if (warp >= N) return;
    int lane = threadIdx.x & 31;
    int half = lane >> 4, l16 = lane & 15;
    int beg = g_rowptr[warp];
    int cnt = g_deg[warp];
    const float4* hp = (const float4*)g_hp;
    float4 a0 = make_float4(0.f, 0.f, 0.f, 0.f);
    float4 a1 = a0, a2 = a0, a3 = a0;
    if (half == 0) a0 = hp[warp * 16 + l16];   // self term on half 0

    for (int b = 0; b < cnt; b += 32) {
        int idx = b + lane;
        int sl  = (idx < cnt) ? __ldg(&g_csr[beg + idx]) : 0;
        int m   = min(32, cnt - b);
        int j   = 0;
        for (; j + 7 < m; j += 8) {            // 8 edges: 4 shfl + 4 LDG.128
            int s0 = __shfl_sync(0xffffffffu, sl, j + half);
            int s1 = __shfl_sync(0xffffffffu, sl, j + 2 + half);
            int s2 = __shfl_sync(0xffffffffu, sl, j + 4 + half);
            int s3 = __shfl_sync(0xffffffffu, sl, j + 6 + half);
            float4 v0 = __ldg(&hp[s0 * 16 + l16]);
            float4 v1 = __ldg(&hp[s1 * 16 + l16]);
            float4 v2 = __ldg(&hp[s2 * 16 + l16]);
            float4 v3 = __ldg(&hp[s3 * 16 + l16]);
            a0.x += v0.x; a0.y += v0.y; a0.z += v0.z; a0.w += v0.w;
            a1.x += v1.x; a1.y += v1.y; a1.z += v1.z; a1.w += v1.w;
            a2.x += v2.x; a2.y += v2.y; a2.z += v2.z; a2.w += v2.w;
            a3.x += v3.x; a3.y += v3.y; a3.z += v3.z; a3.w += v3.w;
        }
        for (; j + 3 < m; j += 4) {            // 4 edges: 2 shfl + 2 LDG.128
            int s0 = __shfl_sync(0xffffffffu, sl, j + half);
            int s1 = __shfl_sync(0xffffffffu, sl, j + 2 + half);
            float4 v0 = __ldg(&hp[s0 * 16 + l16]);
            float4 v1 = __ldg(&hp[s1 * 16 + l16]);
            a0.x += v0.x; a0.y += v0.y; a0.z += v0.z; a0.w += v0.w;
            a1.x += v1.x; a1.y += v1.y; a1.z += v1.z; a1.w += v1.w;
        }
        for (; j < m; j += 2) {                // tail: up to 2 edges
            int jj = j + half;
            int s0 = __shfl_sync(0xffffffffu, sl, (jj < m) ? jj : 0);
            if (jj < m) {
                float4 v0 = __ldg(&hp[s0 * 16 + l16]);
                a0.x += v0.x; a0.y += v0.y; a0.z += v0.z; a0.w += v0.w;
            }
        }
    }
    a0.x += a1.x + a2.x + a3.x;
    a0.y += a1.y + a2.y + a3.y;
    a0.z += a1.z + a2.z + a3.z;
    a0.w += a1.w + a2.w + a3.w;
    a0.x += __shfl_xor_sync(0xffffffffu, a0.x, 16);
    a0.y += __shfl_xor_sync(0xffffffffu, a0.y, 16);
    a0.z += __shfl_xor_sync(0xffffffffu, a0.z, 16);
    a0.w += __shfl_xor_sync(0xffffffffu, a0.w, 16);
    if (half == 0) {
        float di = g_dinv[warp];
        ((float4*)g_a)[warp * 16 + l16] =
            make_float4(di * a0.x, di * a0.y, di * a0.z, di * a0.w);
    }
}

// hp = dinv * relu(a @ W + bc) ; 64-row tile, 4r x 4c per thread
// W transposed in smem, row stride 68 floats (== 4 mod 32 -> conflict-free LDS.128)
__global__ void k_matmul(const float* __restrict__ W, const float* __restrict__ bc, int N) {
    __shared__ float4 Wt[4][16][17];   // col c = 4*cg + j  ->  Wt[j][cg][k4]
    __shared__ float4 hs[64][16];      // a-tile [row][k4]
    __shared__ float  dv[64];
    __shared__ float  bs[64];
    int tid = threadIdx.x;             // 256 threads
    for (int i = tid; i < H * H; i += 256) {
        int k = i >> 6, c = i & 63;
        ((float*)&Wt[c & 3][c >> 2][0])[k] = W[i];
    }
    int base = blockIdx.x * 64;
    const float4* a4 = (const float4*)g_a;
    for (int i = tid; i < 64 * 16; i += 256) {
        int r = i >> 4, k4 = i & 15;
        int n = base + r;
        hs[r][k4] = (n < N) ? a4[n * 16 + k4] : make_float4(0.f, 0.f, 0.f, 0.f);
    }
    if (tid < 64) {
        bs[tid] = bc[tid];
        int n = base + tid;
        dv[tid] = (n < N) ? g_dinv[n] : 0.f;
    }
    __syncthreads();

    int cg = tid & 15, rg = tid >> 4;
    float4 acc[4];
#pragma unroll
    for (int m = 0; m < 4; m++) acc[m] = make_float4(0.f, 0.f, 0.f, 0.f);

#pragma unroll
    for (int k4 = 0; k4 < 16; k4++) {
        float4 w0 = Wt[0][cg][k4];
        float4 w1 = Wt[1][cg][k4];
        float4 w2 = Wt[2][cg][k4];
        float4 w3 = Wt[3][cg][k4];
#pragma unroll
        for (int m = 0; m < 4; m++) {
            float4 h = hs[rg + 16 * m][k4];
            acc[m].x = fmaf(h.x, w0.x, fmaf(h.y, w0.y, fmaf(h.z, w0.z, fmaf(h.w, w0.w, acc[m].x))));
            acc[m].y = fmaf(h.x, w1.x, fmaf(h.y, w1.y, fmaf(h.z, w1.z, fmaf(h.w, w1.w, acc[m].y))));
            acc[m].z = fmaf(h.x, w2.x, fmaf(h.y, w2.y, fmaf(h.z, w2.z, fmaf(h.w, w2.w, acc[m].z))));
            acc[m].w = fmaf(h.x, w3.x, fmaf(h.y, w3.y, fmaf(h.z, w3.z, fmaf(h.w, w3.w, acc[m].w))));
        }
    }

#pragma unroll
    for (int m = 0; m < 4; m++) {
        int r = rg + 16 * m;
        int n = base + r;
        if (n < N) {
            float d = dv[r];
            float4 o;
            o.x = d * fmaxf(acc[m].x + bs[4 * cg + 0], 0.f);
            o.y = d * fmaxf(acc[m].y + bs[4 * cg + 1], 0.f);
            o.z = d * fmaxf(acc[m].z + bs[4 * cg + 2], 0.f);
            o.w = d * fmaxf(acc[m].w + bs[4 * cg + 3], 0.f);
            ((float4*)g_hp)[n * 16 + cg] = o;
        }
    }
}

// Fused last conv layer + both heads.
__global__ void k_conv_heads(const float* __restrict__ Wc, const float* __restrict__ bc,
                             const float* __restrict__ Wd1, const float* __restrict__ bd1,
                             const float* __restrict__ Wd2, const float* __restrict__ bd2,
                             const float* __restrict__ Wi1, const float* __restrict__ bi1,
                             const float* __restrict__ Wi2, const float* __restrict__ bi2,
                             float* __restrict__ out, int N) {
    __shared__ float4 WtC[4][16][17];
    __shared__ float4 WtH[4][16][17];
    __shared__ float4 hs[64][16];
    __shared__ float  bs[64], b1s[64], w2s[64], b2s[2];
    int tid = threadIdx.x;             // 256 threads
    for (int i = tid; i < H * H; i += 256) {
        int k = i >> 6, c = i & 63;
        ((float*)&WtC[c & 3][c >> 2][0])[k] = Wc[i];
        float wh = (c < 32) ? Wd1[k * 32 + c] : Wi1[k * 32 + (c - 32)];
        ((float*)&WtH[c & 3][c >> 2][0])[k] = wh;
    }
    if (tid < 64) {
        bs[tid]  = bc[tid];
        b1s[tid] = (tid < 32) ? bd1[tid] : bi1[tid - 32];
        w2s[tid] = (tid < 32) ? Wd2[tid] : Wi2[tid - 32];
    }
    if (tid == 0) { b2s[0] = bd2[0]; b2s[1] = bi2[0]; }
    int base = blockIdx.x * 64;
    const float4* a4 = (const float4*)g_a;
    for (int i = tid; i < 64 * 16; i += 256) {
        int r = i >> 4, k4 = i & 15;
        int n = base + r;
        hs[r][k4] = (n < N) ? a4[n * 16 + k4] : make_float4(0.f, 0.f, 0.f, 0.f);
    }
    __syncthreads();

    int cg = tid & 15, rg = tid >> 4;
    float4 acc[4];
#pragma unroll
    for (int m = 0; m < 4; m++) acc[m] = make_float4(0.f, 0.f, 0.f, 0.f);

    // ---- stage 1: conv matmul ----
#pragma unroll
    for (int k4 = 0; k4 < 16; k4++) {
        float4 w0 = WtC[0][cg][k4];
        float4 w1 = WtC[1][cg][k4];
        float4 w2 = WtC[2][cg][k4];
        float4 w3 = WtC[3][cg][k4];
#pragma unroll
        for (int m = 0; m < 4; m++) {
            float4 h = hs[rg + 16 * m][k4];
            acc[m].x = fmaf(h.x, w0.x, fmaf(h.y, w0.y, fmaf(h.z, w0.z, fmaf(h.w, w0.w, acc[m].x))));
            acc[m].y = fmaf(h.x, w1.x, fmaf(h.y, w1.y, fmaf(h.z, w1.z, fmaf(h.w, w1.w, acc[m].y))));
            acc[m].z = fmaf(h.x, w2.x, fmaf(h.y, w2.y, fmaf(h.z, w2.z, fmaf(h.w, w2.w, acc[m].z))));
            acc[m].w = fmaf(h.x, w3.x, fmaf(h.y, w3.y, fmaf(h.z, w3.z, fmaf(h.w, w3.w, acc[m].w))));
        }
    }
    __syncthreads();                   // all hs reads done before overwrite

#pragma unroll
    for (int m = 0; m < 4; m++) {
        float4 o;
        o.x = fmaxf(acc[m].x + bs[4 * cg + 0], 0.f);
        o.y = fmaxf(acc[m].y + bs[4 * cg + 1], 0.f);
        o.z = fmaxf(acc[m].z + bs[4 * cg + 2], 0.f);
        o.w = fmaxf(acc[m].w + bs[4 * cg + 3], 0.f);
        hs[rg + 16 * m][cg] = o;
        acc[m] = make_float4(0.f, 0.f, 0.f, 0.f);
    }
    __syncthreads();

    // ---- stage 2: head layer-1 matmul ----
#pragma unroll
    for (int k4 = 0; k4 < 16; k4++) {
        float4 w0 = WtH[0][cg][k4];
        float4 w1 = WtH[1][cg][k4];
        float4 w2 = WtH[2][cg][k4];
        float4 w3 = WtH[3][cg][k4];
#pragma unroll
        for (int m = 0; m < 4; m++) {
            float4 h = hs[rg + 16 * m][k4];
            acc[m].x = fmaf(h.x, w0.x, fmaf(h.y, w0.y, fmaf(h.z, w0.z, fmaf(h.w, w0.w, acc[m].x))));
            acc[m].y = fmaf(h.x, w1.x, fmaf(h.y, w1.y, fmaf(h.z, w1.z, fmaf(h.w, w1.w, acc[m].y))));
            acc[m].z = fmaf(h.x, w2.x, fmaf(h.y, w2.y, fmaf(h.z, w2.z, fmaf(h.w, w2.w, acc[m].z))));
            acc[m].w = fmaf(h.x, w3.x, fmaf(h.y, w3.y, fmaf(h.z, w3.z, fmaf(h.w, w3.w, acc[m].w))));
        }
    }

    // ---- stage 3: relu(t+b1) . w2, half-warp reduce (16 threads per row) ----
    float w2a = w2s[4 * cg + 0], w2b = w2s[4 * cg + 1];
    float w2c = w2s[4 * cg + 2], w2d = w2s[4 * cg + 3];
    float b1a = b1s[4 * cg + 0], b1b = b1s[4 * cg + 1];
    float b1c = b1s[4 * cg + 2], b1d = b1s[4 * cg + 3];
#pragma unroll
    for (int m = 0; m < 4; m++) {
        int r = rg + 16 * m;
        int n = base + r;
        float local = fmaxf(acc[m].x + b1a, 0.f) * w2a
                    + fmaxf(acc[m].y + b1b, 0.f) * w2b
                    + fmaxf(acc[m].z + b1c, 0.f) * w2c
                    + fmaxf(acc[m].w + b1d, 0.f) * w2d;
        local += __shfl_xor_sync(0xffffffffu, local, 1);
        local += __shfl_xor_sync(0xffffffffu, local, 2);
        local += __shfl_xor_sync(0xffffffffu, local, 4);
        if (n < N) {
            if (cg == 0) out[n]     = local + b2s[0];   // demand    (cols 0-31)
            if (cg == 8) out[N + n] = local + b2s[1];   // inventory (cols 32-63)
        }
    }
}

// ---------------- launch ----------------
extern "C" void kernel_launch(void* const* d_in, const int* in_sizes, int n_in,
                              void* d_out, int out_size) {
    const float* x   = (const float*)d_in[0];
    const int*   ei  = (const int*)  d_in[1];
    const float* Wn  = (const float*)d_in[3];
    const float* bn  = (const float*)d_in[4];
    const float* Wc  = (const float*)d_in[7];
    const float* bc  = (const float*)d_in[8];
    const float* Wd1 = (const float*)d_in[9];
    const float* bd1 = (const float*)d_in[10];
    const float* Wd2 = (const float*)d_in[11];
    const float* bd2 = (const float*)d_in[12];
    const float* Wi1 = (const float*)d_in[13];
    const float* bi1 = (const float*)d_in[14];
    const float* Wi2 = (const float*)d_in[15];
    const float* bi2 = (const float*)d_in[16];
    float* out = (float*)d_out;

    int N = in_sizes[0] / 5;
    int E = in_sizes[1] / 2;
    const int* src = ei;       // edge_index[0]
    const int* dst = ei + E;   // edge_index[1]

    void* degPtr = nullptr;
    cudaGetSymbolAddress(&degPtr, g_deg);
    cudaMemsetAsync(degPtr, 0, (size_t)N * sizeof(int));

    int nb = (N + 1023) / 1024;
    k_count<<<(E + 1023) / 1024, 256>>>(dst, E);   // 4 edges per thread
    k_scan1<<<nb, 1024>>>(N);
    k_scan3<<<nb, 1024>>>(N, E);
    int feWork = (N * H > E) ? N * H : E;
    k_fill_encode<<<(feWork + 255) / 256, 256>>>(src, dst, x, Wn, bn, N, E);

    int gatherBlocks = (N * 32 + 255) / 256;
    int mmBlocks     = (N + 63) / 64;

    k_gather<<<gatherBlocks, 256>>>(N);
    k_matmul<<<mmBlocks, 256>>>(Wc + 0 * H * H, bc + 0 * H, N);
    k_gather<<<gatherBlocks, 256>>>(N);
    k_matmul<<<mmBlocks, 256>>>(Wc + 1 * H * H, bc + 1 * H, N);
    k_gather<<<gatherBlocks, 256>>>(N);
    k_conv_heads<<<mmBlocks, 256>>>(Wc + 2 * H * H, bc + 2 * H,
                                    Wd1, bd1, Wd2, bd2, Wi1, bi1, Wi2, bi2, out, N);
}

// round 12
// speedup vs baseline: 1.0777x; 1.0777x over previous
#include <cuda_runtime.h>
#include <cuda_bf16.h>

// Problem constants (fixed by the dataset)
#define MAXN 100352
#define MAXE 1605632
#define H 64

// ---------------- device scratch (no allocations allowed) ----------------
__device__ float g_hp [MAXN * H];   // pre-scaled features  h' = dinv * h
__device__ float g_a  [MAXN * H];   // aggregated features (gather output)
__device__ int   g_deg   [MAXN];
__device__ float g_dinv  [MAXN];
__device__ int   g_rowptr[MAXN + 1];
__device__ int   g_rank  [MAXE];    // per-edge rank within its dst bucket
__device__ int   g_csr   [MAXE];    // src index per CSR slot (grouped by dst)
__device__ int   g_bsums [1024];

// ---------------- CSR build ----------------

// degree count; atomic return value = edge's rank within its dst bucket
__global__ void k_count(const int* __restrict__ dst, int E) {
    int e = blockIdx.x * blockDim.x + threadIdx.x;
    if (e < E) g_rank[e] = atomicAdd(&g_deg[dst[e]], 1);
}

// exclusive scan of g_deg -> g_rowptr (warp-shuffle scan); also dinv = rsqrt(deg+1)
__global__ void k_scan1(int N) {
    __shared__ int wsum[32];
    int t = threadIdx.x, i = blockIdx.x * 1024 + t;
    int lane = t & 31, wid = t >> 5;
    int v = (i < N) ? g_deg[i] : 0;
    if (i < N) g_dinv[i] = rsqrtf((float)v + 1.0f);
    int x = v;
#pragma unroll
    for (int off = 1; off < 32; off <<= 1) {
        int y = __shfl_up_sync(0xffffffffu, x, off);
        if (lane >= off) x += y;
    }
    if (lane == 31) wsum[wid] = x;
    __syncthreads();
    if (wid == 0) {
        int w = wsum[lane];
#pragma unroll
        for (int off = 1; off < 32; off <<= 1) {
            int y = __shfl_up_sync(0xffffffffu, w, off);
            if (lane >= off) w += y;
        }
        wsum[lane] = w;
    }
    __syncthreads();
    int boff = (wid > 0) ? wsum[wid - 1] : 0;
    int incl = x + boff;
    if (i < N) g_rowptr[i] = incl - v;          // exclusive
    if (t == 1023) g_bsums[blockIdx.x] = incl;  // block total
}

// adds global block offsets (computed directly from g_bsums).
// Replaces the old scan2+scan3 pair: warp 0 sums bsums[0..b) (<=97 ints).
__global__ void k_scan3(int N, int E) {
    __shared__ int s_off;
    int b = blockIdx.x, t = threadIdx.x;
    if (t < 32) {
        int sum = 0;
        for (int j = t; j < b; j += 32) sum += g_bsums[j];
#pragma unroll
        for (int off = 16; off; off >>= 1)
            sum += __shfl_xor_sync(0xffffffffu, sum, off);
        if (t == 0) s_off = sum;
    }
    __syncthreads();
    int i = b * 1024 + t;
    if (i < N) g_rowptr[i] += s_off;
    if (i == 0) g_rowptr[N] = E;
}

// fused: CSR fill (idx < E, atomic-free via precomputed ranks) + node encoder.
// hp = dinv * relu(x @ Wn + bn)
__global__ void k_fill_encode(const int* __restrict__ src, const int* __restrict__ dst,
                              const float* __restrict__ x,
                              const float* __restrict__ Wn,
                              const float* __restrict__ bn, int N, int E) {
    int idx = blockIdx.x * blockDim.x + threadIdx.x;
    if (idx < E) {
        int d = __ldg(&dst[idx]);
        g_csr[g_rowptr[d] + g_rank[idx]] = __ldg(&src[idx]);
    }
    if (idx < N * H) {
        int n = idx >> 6, c = idx & 63;
        const float* xr = x + n * 5;
        float acc = __ldg(&bn[c]);
#pragma unroll
        for (int j = 0; j < 5; j++) acc = fmaf(__ldg(&xr[j]), __ldg(&Wn[j * H + c]), acc);
        g_hp[idx] = g_dinv[n] * fmaxf(acc, 0.0f);
    }
}

// ---------------- feature pipeline ----------------

// a_n = dinv_n * ( sum_{s in in(n)} h'_s + h'_n ) ; warp per node.
// Half-warp per edge: lanes 0-15 even edges, 16-31 odd edges, float4/lane.
// (exact R6/R9 4-edge version — best measured)
__global__ void k_gather(int N) {
    int warp = (blockIdx.x * blockDim.x + threadIdx.x) >> 5;
    if (warp >= N) return;
    int lane = threadIdx.x & 31;
    int half = lane >> 4;          // 0 or 1
    int l16  = lane & 15;
    int beg = g_rowptr[warp];
    int cnt = g_deg[warp];
    const float4* hp = (const float4*)g_hp;
    float4 a0 = make_float4(0.f, 0.f, 0.f, 0.f);
    float4 a1 = a0;
    if (half == 0) a0 = hp[warp * 16 + l16];   // self term on half 0

    for (int base = 0; base < cnt; base += 32) {
        int idx = base + lane;
        int sl  = (idx < cnt) ? __ldg(&g_csr[beg + idx]) : 0;
        int m   = min(32, cnt - base);
        int j   = 0;
        for (; j + 3 < m; j += 4) {            // 4 edges per iter: 2 shfl + 2 LDG.128
            int s0 = __shfl_sync(0xffffffffu, sl, j + half);
            int s1 = __shfl_sync(0xffffffffu, sl, j + 2 + half);
            float4 v0 = __ldg(&hp[s0 * 16 + l16]);
            float4 v1 = __ldg(&hp[s1 * 16 + l16]);
            a0.x += v0.x; a0.y += v0.y; a0.z += v0.z; a0.w += v0.w;
            a1.x += v1.x; a1.y += v1.y; a1.z += v1.z; a1.w += v1.w;
        }
        for (; j < m; j += 2) {                // tail: up to 2 edges
            int jj = j + half;
            int s0 = __shfl_sync(0xffffffffu, sl, (jj < m) ? jj : 0);
            if (jj < m) {
                float4 v0 = __ldg(&hp[s0 * 16 + l16]);
                a0.x += v0.x; a0.y += v0.y; a0.z += v0.z; a0.w += v0.w;
            }
        }
    }
    a0.x += a1.x; a0.y += a1.y; a0.z += a1.z; a0.w += a1.w;
    a0.x += __shfl_xor_sync(0xffffffffu, a0.x, 16);
    a0.y += __shfl_xor_sync(0xffffffffu, a0.y, 16);
    a0.z += __shfl_xor_sync(0xffffffffu, a0.z, 16);
    a0.w += __shfl_xor_sync(0xffffffffu, a0.w, 16);
    if (half == 0) {
        float di = g_dinv[warp];
        ((float4*)g_a)[warp * 16 + l16] =
            make_float4(di * a0.x, di * a0.y, di * a0.z, di * a0.w);
    }
}

// hp = dinv * relu(a @ W + bc) ; 64-row tile, 4r x 4c per thread
// W transposed in smem, row stride 68 floats (== 4 mod 32 -> conflict-free LDS.128)
__global__ void k_matmul(const float* __restrict__ W, const float* __restrict__ bc, int N) {
    __shared__ float4 Wt[4][16][17];   // col c = 4*cg + j  ->  Wt[j][cg][k4]
    __shared__ float4 hs[64][16];      // a-tile [row][k4]
    __shared__ float  dv[64];
    __shared__ float  bs[64];
    int tid = threadIdx.x;             // 256 threads
    for (int i = tid; i < H * H; i += 256) {
        int k = i >> 6, c = i & 63;
        ((float*)&Wt[c & 3][c >> 2][0])[k] = W[i];
    }
    int base = blockIdx.x * 64;
    const float4* a4 = (const float4*)g_a;
    for (int i = tid; i < 64 * 16; i += 256) {
        int r = i >> 4, k4 = i & 15;
        int n = base + r;
        hs[r][k4] = (n < N) ? a4[n * 16 + k4] : make_float4(0.f, 0.f, 0.f, 0.f);
    }
    if (tid < 64) {
        bs[tid] = bc[tid];
        int n = base + tid;
        dv[tid] = (n < N) ? g_dinv[n] : 0.f;
    }
    __syncthreads();

    int cg = tid & 15, rg = tid >> 4;
    float4 acc[4];
#pragma unroll
    for (int m = 0; m < 4; m++) acc[m] = make_float4(0.f, 0.f, 0.f, 0.f);

#pragma unroll
    for (int k4 = 0; k4 < 16; k4++) {
        float4 w0 = Wt[0][cg][k4];
        float4 w1 = Wt[1][cg][k4];
        float4 w2 = Wt[2][cg][k4];
        float4 w3 = Wt[3][cg][k4];
#pragma unroll
        for (int m = 0; m < 4; m++) {
            float4 h = hs[rg + 16 * m][k4];
            acc[m].x = fmaf(h.x, w0.x, fmaf(h.y, w0.y, fmaf(h.z, w0.z, fmaf(h.w, w0.w, acc[m].x))));
            acc[m].y = fmaf(h.x, w1.x, fmaf(h.y, w1.y, fmaf(h.z, w1.z, fmaf(h.w, w1.w, acc[m].y))));
            acc[m].z = fmaf(h.x, w2.x, fmaf(h.y, w2.y, fmaf(h.z, w2.z, fmaf(h.w, w2.w, acc[m].z))));
            acc[m].w = fmaf(h.x, w3.x, fmaf(h.y, w3.y, fmaf(h.z, w3.z, fmaf(h.w, w3.w, acc[m].w))));
        }
    }

#pragma unroll
    for (int m = 0; m < 4; m++) {
        int r = rg + 16 * m;
        int n = base + r;
        if (n < N) {
            float d = dv[r];
            float4 o;
            o.x = d * fmaxf(acc[m].x + bs[4 * cg + 0], 0.f);
            o.y = d * fmaxf(acc[m].y + bs[4 * cg + 1], 0.f);
            o.z = d * fmaxf(acc[m].z + bs[4 * cg + 2], 0.f);
            o.w = d * fmaxf(acc[m].w + bs[4 * cg + 3], 0.f);
            ((float4*)g_hp)[n * 16 + cg] = o;
        }
    }
}

// Fused last conv layer + both heads.
__global__ void k_conv_heads(const float* __restrict__ Wc, const float* __restrict__ bc,
                             const float* __restrict__ Wd1, const float* __restrict__ bd1,
                             const float* __restrict__ Wd2, const float* __restrict__ bd2,
                             const float* __restrict__ Wi1, const float* __restrict__ bi1,
                             const float* __restrict__ Wi2, const float* __restrict__ bi2,
                             float* __restrict__ out, int N) {
    __shared__ float4 WtC[4][16][17];
    __shared__ float4 WtH[4][16][17];
    __shared__ float4 hs[64][16];
    __shared__ float  bs[64], b1s[64], w2s[64], b2s[2];
    int tid = threadIdx.x;             // 256 threads
    for (int i = tid; i < H * H; i += 256) {
        int k = i >> 6, c = i & 63;
        ((float*)&WtC[c & 3][c >> 2][0])[k] = Wc[i];
        float wh = (c < 32) ? Wd1[k * 32 + c] : Wi1[k * 32 + (c - 32)];
        ((float*)&WtH[c & 3][c >> 2][0])[k] = wh;
    }
    if (tid < 64) {
        bs[tid]  = bc[tid];
        b1s[tid] = (tid < 32) ? bd1[tid] : bi1[tid - 32];
        w2s[tid] = (tid < 32) ? Wd2[tid] : Wi2[tid - 32];
    }
    if (tid == 0) { b2s[0] = bd2[0]; b2s[1] = bi2[0]; }
    int base = blockIdx.x * 64;
    const float4* a4 = (const float4*)g_a;
    for (int i = tid; i < 64 * 16; i += 256) {
        int r = i >> 4, k4 = i & 15;
        int n = base + r;
        hs[r][k4] = (n < N) ? a4[n * 16 + k4] : make_float4(0.f, 0.f, 0.f, 0.f);
    }
    __syncthreads();

    int cg = tid & 15, rg = tid >> 4;
    float4 acc[4];
#pragma unroll
    for (int m = 0; m < 4; m++) acc[m] = make_float4(0.f, 0.f, 0.f, 0.f);

    // ---- stage 1: conv matmul ----
#pragma unroll
    for (int k4 = 0; k4 < 16; k4++) {
        float4 w0 = WtC[0][cg][k4];
        float4 w1 = WtC[1][cg][k4];
        float4 w2 = WtC[2][cg][k4];
        float4 w3 = WtC[3][cg][k4];
#pragma unroll
        for (int m = 0; m < 4; m++) {
            float4 h = hs[rg + 16 * m][k4];
            acc[m].x = fmaf(h.x, w0.x, fmaf(h.y, w0.y, fmaf(h.z, w0.z, fmaf(h.w, w0.w, acc[m].x))));
            acc[m].y = fmaf(h.x, w1.x, fmaf(h.y, w1.y, fmaf(h.z, w1.z, fmaf(h.w, w1.w, acc[m].y))));
            acc[m].z = fmaf(h.x, w2.x, fmaf(h.y, w2.y, fmaf(h.z, w2.z, fmaf(h.w, w2.w, acc[m].z))));
            acc[m].w = fmaf(h.x, w3.x, fmaf(h.y, w3.y, fmaf(h.z, w3.z, fmaf(h.w, w3.w, acc[m].w))));
        }
    }
    __syncthreads();                   // all hs reads done before overwrite

#pragma unroll
    for (int m = 0; m < 4; m++) {
        float4 o;
        o.x = fmaxf(acc[m].x + bs[4 * cg + 0], 0.f);
        o.y = fmaxf(acc[m].y + bs[4 * cg + 1], 0.f);
        o.z = fmaxf(acc[m].z + bs[4 * cg + 2], 0.f);
        o.w = fmaxf(acc[m].w + bs[4 * cg + 3], 0.f);
        hs[rg + 16 * m][cg] = o;
        acc[m] = make_float4(0.f, 0.f, 0.f, 0.f);
    }
    __syncthreads();

    // ---- stage 2: head layer-1 matmul ----
#pragma unroll
    for (int k4 = 0; k4 < 16; k4++) {
        float4 w0 = WtH[0][cg][k4];
        float4 w1 = WtH[1][cg][k4];
        float4 w2 = WtH[2][cg][k4];
        float4 w3 = WtH[3][cg][k4];
#pragma unroll
        for (int m = 0; m < 4; m++) {
            float4 h = hs[rg + 16 * m][k4];
            acc[m].x = fmaf(h.x, w0.x, fmaf(h.y, w0.y, fmaf(h.z, w0.z, fmaf(h.w, w0.w, acc[m].x))));
            acc[m].y = fmaf(h.x, w1.x, fmaf(h.y, w1.y, fmaf(h.z, w1.z, fmaf(h.w, w1.w, acc[m].y))));
            acc[m].z = fmaf(h.x, w2.x, fmaf(h.y, w2.y, fmaf(h.z, w2.z, fmaf(h.w, w2.w, acc[m].z))));
            acc[m].w = fmaf(h.x, w3.x, fmaf(h.y, w3.y, fmaf(h.z, w3.z, fmaf(h.w, w3.w, acc[m].w))));
        }
    }

    // ---- stage 3: relu(t+b1) . w2, half-warp reduce (16 threads per row) ----
    float w2a = w2s[4 * cg + 0], w2b = w2s[4 * cg + 1];
    float w2c = w2s[4 * cg + 2], w2d = w2s[4 * cg + 3];
    float b1a = b1s[4 * cg + 0], b1b = b1s[4 * cg + 1];
    float b1c = b1s[4 * cg + 2], b1d = b1s[4 * cg + 3];
#pragma unroll
    for (int m = 0; m < 4; m++) {
        int r = rg + 16 * m;
        int n = base + r;
        float local = fmaxf(acc[m].x + b1a, 0.f) * w2a
                    + fmaxf(acc[m].y + b1b, 0.f) * w2b
                    + fmaxf(acc[m].z + b1c, 0.f) * w2c
                    + fmaxf(acc[m].w + b1d, 0.f) * w2d;
        local += __shfl_xor_sync(0xffffffffu, local, 1);
        local += __shfl_xor_sync(0xffffffffu, local, 2);
        local += __shfl_xor_sync(0xffffffffu, local, 4);
        if (n < N) {
            if (cg == 0) out[n]     = local + b2s[0];   // demand    (cols 0-31)
            if (cg == 8) out[N + n] = local + b2s[1];   // inventory (cols 32-63)
        }
    }
}

// ---------------- launch ----------------
extern "C" void kernel_launch(void* const* d_in, const int* in_sizes, int n_in,
                              void* d_out, int out_size) {
    const float* x   = (const float*)d_in[0];
    const int*   ei  = (const int*)  d_in[1];
    const float* Wn  = (const float*)d_in[3];
    const float* bn  = (const float*)d_in[4];
    const float* Wc  = (const float*)d_in[7];
    const float* bc  = (const float*)d_in[8];
    const float* Wd1 = (const float*)d_in[9];
    const float* bd1 = (const float*)d_in[10];
    const float* Wd2 = (const float*)d_in[11];
    const float* bd2 = (const float*)d_in[12];
    const float* Wi1 = (const float*)d_in[13];
    const float* bi1 = (const float*)d_in[14];
    const float* Wi2 = (const float*)d_in[15];
    const float* bi2 = (const float*)d_in[16];
    float* out = (float*)d_out;

    int N = in_sizes[0] / 5;
    int E = in_sizes[1] / 2;
    const int* src = ei;       // edge_index[0]
    const int* dst = ei + E;   // edge_index[1]

    void* degPtr = nullptr;
    cudaGetSymbolAddress(&degPtr, g_deg);
    cudaMemsetAsync(degPtr, 0, (size_t)N * sizeof(int));

    int nb = (N + 1023) / 1024;
    k_count<<<(E + 255) / 256, 256>>>(dst, E);
    k_scan1<<<nb, 1024>>>(N);
    k_scan3<<<nb, 1024>>>(N, E);
    int feWork = (N * H > E) ? N * H : E;
    k_fill_encode<<<(feWork + 255) / 256, 256>>>(src, dst, x, Wn, bn, N, E);

    int gatherBlocks = (N * 32 + 255) / 256;
    int mmBlocks     = (N + 63) / 64;

    k_gather<<<gatherBlocks, 256>>>(N);
    k_matmul<<<mmBlocks, 256>>>(Wc + 0 * H * H, bc + 0 * H, N);
    k_gather<<<gatherBlocks, 256>>>(N);
    k_matmul<<<mmBlocks, 256>>>(Wc + 1 * H * H, bc + 1 * H, N);
    k_gather<<<gatherBlocks, 256>>>(N);
    k_conv_heads<<<mmBlocks, 256>>>(Wc + 2 * H * H, bc + 2 * H,
                                    Wd1, bd1, Wd2, bd2, Wi1, bi1, Wi2, bi2, out, N);
}

// round 16
// speedup vs baseline: 1.1286x; 1.0472x over previous
#include <cuda_runtime.h>
#include <cuda_bf16.h>

// Problem constants (fixed by the dataset)
#define MAXN 100352
#define MAXE 1605632
#define H 64

// ---------------- device scratch (no allocations allowed) ----------------
__device__ float g_hp [MAXN * H];   // pre-scaled features  h' = dinv * h
__device__ float g_a  [MAXN * H];   // aggregated features (gather output)
__device__ int   g_deg   [MAXN];
__device__ float g_dinv  [MAXN];
__device__ int   g_rowptr[MAXN + 1];
__device__ int   g_cursor[MAXN];
__device__ int   g_csr   [MAXE];    // src index per CSR slot (grouped by dst)
__device__ int   g_bsums [1024];

// ---------------- CSR build ----------------

// plain degree count: return value unused -> compiles to REDG (no round trip)
__global__ void k_count(const int* __restrict__ dst, int E) {
    int e = blockIdx.x * blockDim.x + threadIdx.x;
    if (e < E) atomicAdd(&g_deg[dst[e]], 1);
}

// exclusive scan of g_deg -> g_rowptr (warp-shuffle scan); also dinv = rsqrt(deg+1)
__global__ void k_scan1(int N) {
    __shared__ int wsum[32];
    int t = threadIdx.x, i = blockIdx.x * 1024 + t;
    int lane = t & 31, wid = t >> 5;
    int v = (i < N) ? g_deg[i] : 0;
    if (i < N) g_dinv[i] = rsqrtf((float)v + 1.0f);
    int x = v;
#pragma unroll
    for (int off = 1; off < 32; off <<= 1) {
        int y = __shfl_up_sync(0xffffffffu, x, off);
        if (lane >= off) x += y;
    }
    if (lane == 31) wsum[wid] = x;
    __syncthreads();
    if (wid == 0) {
        int w = wsum[lane];
#pragma unroll
        for (int off = 1; off < 32; off <<= 1) {
            int y = __shfl_up_sync(0xffffffffu, w, off);
            if (lane >= off) w += y;
        }
        wsum[lane] = w;
    }
    __syncthreads();
    int boff = (wid > 0) ? wsum[wid - 1] : 0;
    int incl = x + boff;
    if (i < N) g_rowptr[i] = incl - v;          // exclusive
    if (t == 1023) g_bsums[blockIdx.x] = incl;  // block total
}

// adds global block offsets (computed directly from g_bsums) + inits cursors.
// Replaces the old scan2+scan3 pair (removes a grid=1 serializing kernel):
// warp 0 of block b sums bsums[0..b) (<=97 ints).
__global__ void k_scan3(int N, int E) {
    __shared__ int s_off;
    int b = blockIdx.x, t = threadIdx.x;
    if (t < 32) {
        int sum = 0;
        for (int j = t; j < b; j += 32) sum += g_bsums[j];
#pragma unroll
        for (int off = 16; off; off >>= 1)
            sum += __shfl_xor_sync(0xffffffffu, sum, off);
        if (t == 0) s_off = sum;
    }
    __syncthreads();
    int i = b * 1024 + t;
    if (i < N) {
        int rp = g_rowptr[i] + s_off;
        g_rowptr[i] = rp;
        g_cursor[i] = rp;                       // fill cursors start at row base
    }
    if (i == 0) g_rowptr[N] = E;
}

// fused: CSR fill (idx < E) + node encoder (idx < N*H).
// hp = dinv * relu(x @ Wn + bn)
__global__ void k_fill_encode(const int* __restrict__ src, const int* __restrict__ dst,
                              const float* __restrict__ x,
                              const float* __restrict__ Wn,
                              const float* __restrict__ bn, int N, int E) {
    int idx = blockIdx.x * blockDim.x + threadIdx.x;
    if (idx < E) {
        int pos = atomicAdd(&g_cursor[dst[idx]], 1);
        g_csr[pos] = src[idx];
    }
    if (idx < N * H) {
        int n = idx >> 6, c = idx & 63;
        const float* xr = x + n * 5;
        float acc = __ldg(&bn[c]);
#pragma unroll
        for (int j = 0; j < 5; j++) acc = fmaf(__ldg(&xr[j]), __ldg(&Wn[j * H + c]), acc);
        g_hp[idx] = g_dinv[n] * fmaxf(acc, 0.0f);
    }
}

// ---------------- feature pipeline ----------------

// a_n = dinv_n * ( sum_{s in in(n)} h'_s + h'_n ) ; warp per node.
// Half-warp per edge: lanes 0-15 even edges, 16-31 odd edges, float4/lane.
// (exact R6/R9 4-edge version — best measured)
__global__ void k_gather(int N) {
    int warp = (blockIdx.x * blockDim.x + threadIdx.x) >> 5;
    if (warp >= N) return;
    int lane = threadIdx.x & 31;
    int half = lane >> 4;          // 0 or 1
    int l16  = lane & 15;
    int beg = g_rowptr[warp];
    int cnt = g_deg[warp];
    const float4* hp = (const float4*)g_hp;
    float4 a0 = make_float4(0.f, 0.f, 0.f, 0.f);
    float4 a1 = a0;
    if (half == 0) a0 = hp[warp * 16 + l16];   // self term on half 0

    for (int base = 0; base < cnt; base += 32) {
        int idx = base + lane;
        int sl  = (idx < cnt) ? __ldg(&g_csr[beg + idx]) : 0;
        int m   = min(32, cnt - base);
        int j   = 0;
        for (; j + 3 < m; j += 4) {            // 4 edges per iter: 2 shfl + 2 LDG.128
            int s0 = __shfl_sync(0xffffffffu, sl, j + half);
            int s1 = __shfl_sync(0xffffffffu, sl, j + 2 + half);
            float4 v0 = __ldg(&hp[s0 * 16 + l16]);
            float4 v1 = __ldg(&hp[s1 * 16 + l16]);
            a0.x += v0.x; a0.y += v0.y; a0.z += v0.z; a0.w += v0.w;
            a1.x += v1.x; a1.y += v1.y; a1.z += v1.z; a1.w += v1.w;
        }
        for (; j < m; j += 2) {                // tail: up to 2 edges
            int jj = j + half;
            int s0 = __shfl_sync(0xffffffffu, sl, (jj < m) ? jj : 0);
            if (jj < m) {
                float4 v0 = __ldg(&hp[s0 * 16 + l16]);
                a0.x += v0.x; a0.y += v0.y; a0.z += v0.z; a0.w += v0.w;
            }
        }
    }
    a0.x += a1.x; a0.y += a1.y; a0.z += a1.z; a0.w += a1.w;
    a0.x += __shfl_xor_sync(0xffffffffu, a0.x, 16);
    a0.y += __shfl_xor_sync(0xffffffffu, a0.y, 16);
    a0.z += __shfl_xor_sync(0xffffffffu, a0.z, 16);
    a0.w += __shfl_xor_sync(0xffffffffu, a0.w, 16);
    if (half == 0) {
        float di = g_dinv[warp];
        ((float4*)g_a)[warp * 16 + l16] =
            make_float4(di * a0.x, di * a0.y, di * a0.z, di * a0.w);
    }
}

// hp = dinv * relu(a @ W + bc) ; 64-row tile, 4r x 4c per thread
// W transposed in smem, row stride 68 floats (== 4 mod 32 -> conflict-free LDS.128)
__global__ void k_matmul(const float* __restrict__ W, const float* __restrict__ bc, int N) {
    __shared__ float4 Wt[4][16][17];   // col c = 4*cg + j  ->  Wt[j][cg][k4]
    __shared__ float4 hs[64][16];      // a-tile [row][k4]
    __shared__ float  dv[64];
    __shared__ float  bs[64];
    int tid = threadIdx.x;             // 256 threads
    for (int i = tid; i < H * H; i += 256) {
        int k = i >> 6, c = i & 63;
        ((float*)&Wt[c & 3][c >> 2][0])[k] = W[i];
    }
    int base = blockIdx.x * 64;
    const float4* a4 = (const float4*)g_a;
    for (int i = tid; i < 64 * 16; i += 256) {
        int r = i >> 4, k4 = i & 15;
        int n = base + r;
        hs[r][k4] = (n < N) ? a4[n * 16 + k4] : make_float4(0.f, 0.f, 0.f, 0.f);
    }
    if (tid < 64) {
        bs[tid] = bc[tid];
        int n = base + tid;
        dv[tid] = (n < N) ? g_dinv[n] : 0.f;
    }
    __syncthreads();

    int cg = tid & 15, rg = tid >> 4;
    float4 acc[4];
#pragma unroll
    for (int m = 0; m < 4; m++) acc[m] = make_float4(0.f, 0.f, 0.f, 0.f);

#pragma unroll
    for (int k4 = 0; k4 < 16; k4++) {
        float4 w0 = Wt[0][cg][k4];
        float4 w1 = Wt[1][cg][k4];
        float4 w2 = Wt[2][cg][k4];
        float4 w3 = Wt[3][cg][k4];
#pragma unroll
        for (int m = 0; m < 4; m++) {
            float4 h = hs[rg + 16 * m][k4];
            acc[m].x = fmaf(h.x, w0.x, fmaf(h.y, w0.y, fmaf(h.z, w0.z, fmaf(h.w, w0.w, acc[m].x))));
            acc[m].y = fmaf(h.x, w1.x, fmaf(h.y, w1.y, fmaf(h.z, w1.z, fmaf(h.w, w1.w, acc[m].y))));
            acc[m].z = fmaf(h.x, w2.x, fmaf(h.y, w2.y, fmaf(h.z, w2.z, fmaf(h.w, w2.w, acc[m].z))));
            acc[m].w = fmaf(h.x, w3.x, fmaf(h.y, w3.y, fmaf(h.z, w3.z, fmaf(h.w, w3.w, acc[m].w))));
        }
    }

#pragma unroll
    for (int m = 0; m < 4; m++) {
        int r = rg + 16 * m;
        int n = base + r;
        if (n < N) {
            float d = dv[r];
            float4 o;
            o.x = d * fmaxf(acc[m].x + bs[4 * cg + 0], 0.f);
            o.y = d * fmaxf(acc[m].y + bs[4 * cg + 1], 0.f);
            o.z = d * fmaxf(acc[m].z + bs[4 * cg + 2], 0.f);
            o.w = d * fmaxf(acc[m].w + bs[4 * cg + 3], 0.f);
            ((float4*)g_hp)[n * 16 + cg] = o;
        }
    }
}

// Fused last conv layer + both heads.
__global__ void k_conv_heads(const float* __restrict__ Wc, const float* __restrict__ bc,
                             const float* __restrict__ Wd1, const float* __restrict__ bd1,
                             const float* __restrict__ Wd2, const float* __restrict__ bd2,
                             const float* __restrict__ Wi1, const float* __restrict__ bi1,
                             const float* __restrict__ Wi2, const float* __restrict__ bi2,
                             float* __restrict__ out, int N) {
    __shared__ float4 WtC[4][16][17];
    __shared__ float4 WtH[4][16][17];
    __shared__ float4 hs[64][16];
    __shared__ float  bs[64], b1s[64], w2s[64], b2s[2];
    int tid = threadIdx.x;             // 256 threads
    for (int i = tid; i < H * H; i += 256) {
        int k = i >> 6, c = i & 63;
        ((float*)&WtC[c & 3][c >> 2][0])[k] = Wc[i];
        float wh = (c < 32) ? Wd1[k * 32 + c] : Wi1[k * 32 + (c - 32)];
        ((float*)&WtH[c & 3][c >> 2][0])[k] = wh;
    }
    if (tid < 64) {
        bs[tid]  = bc[tid];
        b1s[tid] = (tid < 32) ? bd1[tid] : bi1[tid - 32];
        w2s[tid] = (tid < 32) ? Wd2[tid] : Wi2[tid - 32];
    }
    if (tid == 0) { b2s[0] = bd2[0]; b2s[1] = bi2[0]; }
    int base = blockIdx.x * 64;
    const float4* a4 = (const float4*)g_a;
    for (int i = tid; i < 64 * 16; i += 256) {
        int r = i >> 4, k4 = i & 15;
        int n = base + r;
        hs[r][k4] = (n < N) ? a4[n * 16 + k4] : make_float4(0.f, 0.f, 0.f, 0.f);
    }
    __syncthreads();

    int cg = tid & 15, rg = tid >> 4;
    float4 acc[4];
#pragma unroll
    for (int m = 0; m < 4; m++) acc[m] = make_float4(0.f, 0.f, 0.f, 0.f);

    // ---- stage 1: conv matmul ----
#pragma unroll
    for (int k4 = 0; k4 < 16; k4++) {
        float4 w0 = WtC[0][cg][k4];
        float4 w1 = WtC[1][cg][k4];
        float4 w2 = WtC[2][cg][k4];
        float4 w3 = WtC[3][cg][k4];
#pragma unroll
        for (int m = 0; m < 4; m++) {
            float4 h = hs[rg + 16 * m][k4];
            acc[m].x = fmaf(h.x, w0.x, fmaf(h.y, w0.y, fmaf(h.z, w0.z, fmaf(h.w, w0.w, acc[m].x))));
            acc[m].y = fmaf(h.x, w1.x, fmaf(h.y, w1.y, fmaf(h.z, w1.z, fmaf(h.w, w1.w, acc[m].y))));
            acc[m].z = fmaf(h.x, w2.x, fmaf(h.y, w2.y, fmaf(h.z, w2.z, fmaf(h.w, w2.w, acc[m].z))));
            acc[m].w = fmaf(h.x, w3.x, fmaf(h.y, w3.y, fmaf(h.z, w3.z, fmaf(h.w, w3.w, acc[m].w))));
        }
    }
    __syncthreads();                   // all hs reads done before overwrite

#pragma unroll
    for (int m = 0; m < 4; m++) {
        float4 o;
        o.x = fmaxf(acc[m].x + bs[4 * cg + 0], 0.f);
        o.y = fmaxf(acc[m].y + bs[4 * cg + 1], 0.f);
        o.z = fmaxf(acc[m].z + bs[4 * cg + 2], 0.f);
        o.w = fmaxf(acc[m].w + bs[4 * cg + 3], 0.f);
        hs[rg + 16 * m][cg] = o;
        acc[m] = make_float4(0.f, 0.f, 0.f, 0.f);
    }
    __syncthreads();

    // ---- stage 2: head layer-1 matmul ----
#pragma unroll
    for (int k4 = 0; k4 < 16; k4++) {
        float4 w0 = WtH[0][cg][k4];
        float4 w1 = WtH[1][cg][k4];
        float4 w2 = WtH[2][cg][k4];
        float4 w3 = WtH[3][cg][k4];
#pragma unroll
        for (int m = 0; m < 4; m++) {
            float4 h = hs[rg + 16 * m][k4];
            acc[m].x = fmaf(h.x, w0.x, fmaf(h.y, w0.y, fmaf(h.z, w0.z, fmaf(h.w, w0.w, acc[m].x))));
            acc[m].y = fmaf(h.x, w1.x, fmaf(h.y, w1.y, fmaf(h.z, w1.z, fmaf(h.w, w1.w, acc[m].y))));
            acc[m].z = fmaf(h.x, w2.x, fmaf(h.y, w2.y, fmaf(h.z, w2.z, fmaf(h.w, w2.w, acc[m].z))));
            acc[m].w = fmaf(h.x, w3.x, fmaf(h.y, w3.y, fmaf(h.z, w3.z, fmaf(h.w, w3.w, acc[m].w))));
        }
    }

    // ---- stage 3: relu(t+b1) . w2, half-warp reduce (16 threads per row) ----
    float w2a = w2s[4 * cg + 0], w2b = w2s[4 * cg + 1];
    float w2c = w2s[4 * cg + 2], w2d = w2s[4 * cg + 3];
    float b1a = b1s[4 * cg + 0], b1b = b1s[4 * cg + 1];
    float b1c = b1s[4 * cg + 2], b1d = b1s[4 * cg + 3];
#pragma unroll
    for (int m = 0; m < 4; m++) {
        int r = rg + 16 * m;
        int n = base + r;
        float local = fmaxf(acc[m].x + b1a, 0.f) * w2a
                    + fmaxf(acc[m].y + b1b, 0.f) * w2b
                    + fmaxf(acc[m].z + b1c, 0.f) * w2c
                    + fmaxf(acc[m].w + b1d, 0.f) * w2d;
        local += __shfl_xor_sync(0xffffffffu, local, 1);
        local += __shfl_xor_sync(0xffffffffu, local, 2);
        local += __shfl_xor_sync(0xffffffffu, local, 4);
        if (n < N) {
            if (cg == 0) out[n]     = local + b2s[0];   // demand    (cols 0-31)
            if (cg == 8) out[N + n] = local + b2s[1];   // inventory (cols 32-63)
        }
    }
}

// ---------------- launch ----------------
extern "C" void kernel_launch(void* const* d_in, const int* in_sizes, int n_in,
                              void* d_out, int out_size) {
    const float* x   = (const float*)d_in[0];
    const int*   ei  = (const int*)  d_in[1];
    const float* Wn  = (const float*)d_in[3];
    const float* bn  = (const float*)d_in[4];
    const float* Wc  = (const float*)d_in[7];
    const float* bc  = (const float*)d_in[8];
    const float* Wd1 = (const float*)d_in[9];
    const float* bd1 = (const float*)d_in[10];
    const float* Wd2 = (const float*)d_in[11];
    const float* bd2 = (const float*)d_in[12];
    const float* Wi1 = (const float*)d_in[13];
    const float* bi1 = (const float*)d_in[14];
    const float* Wi2 = (const float*)d_in[15];
    const float* bi2 = (const float*)d_in[16];
    float* out = (float*)d_out;

    int N = in_sizes[0] / 5;
    int E = in_sizes[1] / 2;
    const int* src = ei;       // edge_index[0]
    const int* dst = ei + E;   // edge_index[1]

    void* degPtr = nullptr;
    cudaGetSymbolAddress(&degPtr, g_deg);
    cudaMemsetAsync(degPtr, 0, (size_t)N * sizeof(int));

    int nb = (N + 1023) / 1024;
    k_count<<<(E + 255) / 256, 256>>>(dst, E);
    k_scan1<<<nb, 1024>>>(N);
    k_scan3<<<nb, 1024>>>(N, E);
    int feWork = (N * H > E) ? N * H : E;
    k_fill_encode<<<(feWork + 255) / 256, 256>>>(src, dst, x, Wn, bn, N, E);

    int gatherBlocks = (N * 32 + 255) / 256;
    int mmBlocks     = (N + 63) / 64;

    k_gather<<<gatherBlocks, 256>>>(N);
    k_matmul<<<mmBlocks, 256>>>(Wc + 0 * H * H, bc + 0 * H, N);
    k_gather<<<gatherBlocks, 256>>>(N);
    k_matmul<<<mmBlocks, 256>>>(Wc + 1 * H * H, bc + 1 * H, N);
    k_gather<<<gatherBlocks, 256>>>(N);
    k_conv_heads<<<mmBlocks, 256>>>(Wc + 2 * H * H, bc + 2 * H,
                                    Wd1, bd1, Wd2, bd2, Wi1, bi1, Wi2, bi2, out, N);
}